// round 4
// baseline (speedup 1.0000x reference)
#include <cuda_runtime.h>
#include <cstdint>

// PreEncoder: per input fp32 f, emit 16 fp32 values in {-1,+1} encoding the
// quirky fp16-style bit pattern of the reference (sign of f+0.001, exp wrap
// mod 32, truncated 10-bit mantissa; NaN->0x7E00, +/-inf->0x7C00/0xFC00;
// exact tie f+0.001==0 -> 0.0 in the sign slot).
//
// R3: double-buffered bulk-store pipeline. 16 KB TMA ops (large => amortized
// fixed cost, the R2 lesson) with NO blocking drain in steady state: each CTA
// computes tile k+1 while tile k's cp.async.bulk drains; buffer reuse is
// gated by wait_group.read 1 two iterations later.

constexpr int THREADS    = 256;
constexpr int TILE_IN    = 256;              // inputs per tile (1/thread)
constexpr int TILE_FLOATS = TILE_IN * 16;    // 4096 floats = 16 KB

__device__ __forceinline__ void encode16(float f, float* __restrict__ v)
{
    uint32_t au = __float_as_uint(f) & 0x7FFFFFFFu;
    uint32_t W;
    bool normal = (au < 0x7F800000u);
    float s_val = -1.0f;

    if (!normal) {
        if (au > 0x7F800000u) {
            W = 0x7E00u;                                          // NaN
        } else {
            W = (__float_as_uint(f) >> 31) ? 0xFC00u : 0x7C00u;   // +/- inf
        }
    } else {
        float fp = f + 0.001f;
        uint32_t s = (fp < 0.0f) ? 1u : 0u;
        s_val = (fp < 0.0f) ? 1.0f : ((fp == 0.0f) ? 0.0f : -1.0f);

        int e_dec;
        uint32_t T;
        if (au == 0u) {
            e_dec = 0;                       // log2(0) clamped to -15
            T = 0u;
        } else {
            int be = (int)(au >> 23);
            if (be != 0) {
                e_dec = be - 112;            // (be-127)+15
                T = (au >> 13) & 0x3FFu;     // top 10 mantissa bits (truncate)
            } else {
                int lz = __clz(au);          // subnormal input
                e_dec = (31 - lz) - 134;
                T = ((au << lz) << 1) >> 22;
            }
        }
        W = (s << 15) | (((uint32_t)e_dec & 31u) << 10) | T;
    }

    uint32_t nW = ~W;
#pragma unroll
    for (int k = 0; k < 16; k++) {
        // sign bit of output = !bit(15-k); magnitude always 1.0f
        uint32_t sgn = (nW << (16 + k)) & 0x80000000u;
        v[k] = __uint_as_float(0x3F800000u | sgn);
    }
    if (normal) v[0] = s_val;   // exact-tie case can be 0.0
}

__global__ void __launch_bounds__(THREADS) PreEncoder_69157563400693_kernel(
    const float* __restrict__ x, float* __restrict__ out, int n, int ntiles)
{
    __shared__ alignas(128) float buf[2][TILE_FLOATS];   // 2 x 16 KB

    int it = 0;
    for (int t = blockIdx.x; t < ntiles; t += gridDim.x, ++it) {
        int p = it & 1;

        // gate buffer reuse: the bulk issued 2 iterations ago (same buffer)
        // must have finished READING smem; allow 1 group still in flight.
        if (it >= 2 && threadIdx.x == 0) {
            asm volatile("cp.async.bulk.wait_group.read 1;" ::: "memory");
        }
        __syncthreads();

        int base = t * TILE_IN;
        int i = base + (int)threadIdx.x;
        float f = (i < n) ? x[i] : 0.0f;

        float v[16];
        encode16(f, v);

        float4* s = reinterpret_cast<float4*>(&buf[p][(size_t)threadIdx.x * 16]);
        s[0] = make_float4(v[0],  v[1],  v[2],  v[3]);
        s[1] = make_float4(v[4],  v[5],  v[6],  v[7]);
        s[2] = make_float4(v[8],  v[9],  v[10], v[11]);
        s[3] = make_float4(v[12], v[13], v[14], v[15]);

        __syncthreads();

        if (threadIdx.x == 0) {
            int valid = n - base;
            if (valid > TILE_IN) valid = TILE_IN;
            uint32_t bytes = (uint32_t)valid * 64u;
            uint32_t saddr;
            asm("{ .reg .u64 tt; cvta.to.shared.u64 tt, %1; cvt.u32.u64 %0, tt; }"
                : "=r"(saddr) : "l"(&buf[p][0]));
            float* gdst = out + (size_t)base * 16;
            asm volatile("fence.proxy.async.shared::cta;" ::: "memory");
            asm volatile(
                "cp.async.bulk.global.shared::cta.bulk_group [%0], [%1], %2;"
                :: "l"(gdst), "r"(saddr), "r"(bytes) : "memory");
            asm volatile("cp.async.bulk.commit_group;" ::: "memory");
        }
    }

    // drain: SMEM must stay alive until all bulk reads complete
    if (threadIdx.x == 0) {
        asm volatile("cp.async.bulk.wait_group.read 0;" ::: "memory");
    }
    __syncthreads();
}

extern "C" void kernel_launch(void* const* d_in, const int* in_sizes, int n_in,
                              void* d_out, int out_size)
{
    const float* x = (const float*)d_in[0];
    float* out = (float*)d_out;
    int n = in_sizes[0];                               // 2,097,152
    int ntiles = (n + TILE_IN - 1) / TILE_IN;          // 8192
    int grid = 148 * 7;                                // 7 CTAs/SM (32KB smem)
    if (grid > ntiles) grid = ntiles;
    PreEncoder_69157563400693_kernel<<<grid, THREADS>>>(x, out, n, ntiles);
}

// round 5
// speedup vs baseline: 1.2428x; 1.2428x over previous
#include <cuda_runtime.h>
#include <cstdint>

// PreEncoder: per input fp32 f, emit 16 fp32 values in {-1,+1} encoding the
// quirky fp16-style bit pattern of the reference (sign of f+0.001, exp wrap
// mod 32, truncated 10-bit mantissa; NaN->0x7E00, +/-inf->0x7C00/0xFC00;
// exact tie f+0.001==0 -> 0.0 in the sign slot).
//
// R4: register-level transpose via warp shuffles -> fully coalesced STG.128
// (each warp store instruction writes 512 contiguous bytes). No SMEM, no
// barriers, no TMA. Fixes the 4x store-wavefront waste that bound R0's L1tex.

constexpr int THREADS = 256;

// Compute the 16-bit pattern W and the sign-slot output value (handles the
// f+0.001 exact-tie -> 0.0 quirk).
__device__ __forceinline__ void encode_pattern(float f, uint32_t& W, float& s_val)
{
    uint32_t au = __float_as_uint(f) & 0x7FFFFFFFu;
    bool normal = (au < 0x7F800000u);

    if (!normal) {
        if (au > 0x7F800000u) {
            W = 0x7E00u;                                          // NaN
        } else {
            W = (__float_as_uint(f) >> 31) ? 0xFC00u : 0x7C00u;   // +/- inf
        }
        s_val = (W & 0x8000u) ? 1.0f : -1.0f;
    } else {
        float fp = f + 0.001f;
        uint32_t s = (fp < 0.0f) ? 1u : 0u;
        s_val = (fp < 0.0f) ? 1.0f : ((fp == 0.0f) ? 0.0f : -1.0f);

        int e_dec;
        uint32_t T;
        if (au == 0u) {
            e_dec = 0;                       // log2(0) clamped to -15
            T = 0u;
        } else {
            int be = (int)(au >> 23);
            if (be != 0) {
                e_dec = be - 112;            // (be-127)+15
                T = (au >> 13) & 0x3FFu;     // top 10 mantissa bits (truncate)
            } else {
                int lz = __clz(au);          // subnormal input
                e_dec = (31 - lz) - 134;
                T = ((au << lz) << 1) >> 22;
            }
        }
        W = (s << 15) | (((uint32_t)e_dec & 31u) << 10) | T;
    }
}

__global__ void __launch_bounds__(THREADS) PreEncoder_69157563400693_kernel(
    const float* __restrict__ x, float* __restrict__ out, int n)
{
    const int tid  = blockIdx.x * blockDim.x + threadIdx.x;
    const int lane = (int)threadIdx.x & 31;
    const int wbase = tid - lane;            // warp's first input index

    float f = (tid < n) ? x[tid] : 0.0f;

    uint32_t W;
    float s_val;
    encode_pattern(f, W, s_val);

    if (wbase + 32 <= n) {
        // Full warp: transposed, fully-coalesced stores.
        // float4 slot j (= r*32 + lane) of the warp's 2KB region holds
        // quarter (j&3) of input (j>>2). Lane l needs data from source lane
        // r*8 + (l>>2).
        float4* obase = reinterpret_cast<float4*>(out) + (size_t)wbase * 4;
        const int q = lane & 3;              // which quarter this lane expands
        const int srclo = lane >> 2;

#pragma unroll
        for (int r = 0; r < 4; r++) {
            int src = r * 8 + srclo;
            uint32_t Wj = __shfl_sync(0xFFFFFFFFu, W, src);
            float    sj = __shfl_sync(0xFFFFFFFFu, s_val, src);

            // bits k = 4q..4q+3 ; output sign = !bit(15-k), magnitude 1.0
            uint32_t nt = (~Wj) << (16 + 4 * q);
            float4 val;
            val.x = __uint_as_float(0x3F800000u | ( nt        & 0x80000000u));
            val.y = __uint_as_float(0x3F800000u | ((nt << 1)  & 0x80000000u));
            val.z = __uint_as_float(0x3F800000u | ((nt << 2)  & 0x80000000u));
            val.w = __uint_as_float(0x3F800000u | ((nt << 3)  & 0x80000000u));
            if (q == 0) val.x = sj;          // sign slot (can be 0.0 on tie)

            obase[r * 32 + lane] = val;
        }
    } else if (tid < n) {
        // ragged tail: direct (uncoalesced) stores for this thread's input
        uint32_t nW = ~W;
        float v[16];
#pragma unroll
        for (int k = 0; k < 16; k++) {
            uint32_t sgn = (nW << (16 + k)) & 0x80000000u;
            v[k] = __uint_as_float(0x3F800000u | sgn);
        }
        v[0] = s_val;
        float4* o = reinterpret_cast<float4*>(out) + (size_t)tid * 4;
        o[0] = make_float4(v[0],  v[1],  v[2],  v[3]);
        o[1] = make_float4(v[4],  v[5],  v[6],  v[7]);
        o[2] = make_float4(v[8],  v[9],  v[10], v[11]);
        o[3] = make_float4(v[12], v[13], v[14], v[15]);
    }
}

extern "C" void kernel_launch(void* const* d_in, const int* in_sizes, int n_in,
                              void* d_out, int out_size)
{
    const float* x = (const float*)d_in[0];
    float* out = (float*)d_out;
    int n = in_sizes[0];                     // 2,097,152
    int blocks = (n + THREADS - 1) / THREADS;
    PreEncoder_69157563400693_kernel<<<blocks, THREADS>>>(x, out, n);
}